// round 12
// baseline (speedup 1.0000x reference)
#include <cuda_runtime.h>
#include <cuda_bf16.h>
#include <math.h>

// Problem constants
#define H2 48
#define W2 48
#define NPIX 2304           // 48*48
#define CCH 128             // channels
#define NB 2                // batch
#define H1 96
#define W1 96
#define NJ 2048             // 16 * 128  ((a,b) x c)
#define KP 1152             // 9 * 128 patch length
#define OPIX 9216           // 96*96

// ---------------- scratch (device globals; no runtime allocation) ----------------
// NOTE: these symbols are ONLY referenced from device code. Passing them as
// kernel arguments from host code passes the HOST shadow address (which GB300's
// ATS happily dereferences into host BSS) — that was the Round 2-11 bug.
__device__ __align__(16) float g_P[(size_t)NB * NPIX * KP];       // im2col3(x2) [n][p][o*128+c]
__device__ __align__(16) float g_S[(size_t)NB * NPIX * NPIX];     // scores S=P P^T [n][p][q]
__device__ __align__(16) float g_att[(size_t)NB * NPIX * NPIX];   // attention   [n][pix][q]
__device__ __align__(16) float g_W[(size_t)NB * NPIX * NJ];       // im2col(x1)  [n][q][(a*4+b)*128+c]
__device__ __align__(16) float g_T[(size_t)NB * NPIX * NJ];       // gemm out    [n][pix][(a*4+b)*128+c]
__device__ __align__(16) float g_y[(size_t)NB * CCH * OPIX];      // paste result [n][c][96*96]
__device__ int g_sel;   // 0: first 4608-tensor is binary mask; 1: it's mask_all

// ---------------- K0: detect which 4608-tensor is the binary mask ----------------
__global__ __launch_bounds__(256) void k_detect(const float* __restrict__ mA) {
    __shared__ int nonbin;
    if (threadIdx.x == 0) nonbin = 0;
    __syncthreads();
    int local = 0;
    for (int i = threadIdx.x; i < NB * NPIX; i += 256) {
        float v = mA[i];
        if (v != 0.0f && v != 1.0f) local = 1;
    }
    if (local) atomicOr(&nonbin, 1);
    __syncthreads();
    if (threadIdx.x == 0) g_sel = nonbin;   // nonbinary -> mA is mask_all
}

// ---------------- K1: im2col 3x3 (pad 1) of x2 -> P ----------------
__global__ __launch_bounds__(256) void k_im2col3(const float* __restrict__ x2) {
    int p = blockIdx.x;
    int n = blockIdx.y;
    int py = p / W2, px = p % W2;
    size_t base = ((size_t)n * NPIX + p) * KP;
    for (int j = threadIdx.x; j < KP; j += 256) {
        int c = j & 127;
        int o = j >> 7;          // 0..8
        int dy = o / 3 - 1, dx = o % 3 - 1;
        int ry = py + dy, rx = px + dx;
        float v = 0.f;
        if ((unsigned)ry < H2 && (unsigned)rx < W2)
            v = x2[((size_t)(n * CCH + c)) * NPIX + ry * W2 + rx];
        g_P[base + j] = v;
    }
}

// ---------------- tiled SGEMM over device-global operands ----------------
// MODE 0 (score): C=g_S[2304x2304] = A=g_P[2304xKP] * B=g_P[2304xKP]^T
// MODE 1 (paste): C=g_T[2304xNJ]   = A=g_att[2304x2304] * B=g_W[2304xNJ]
// Tiles 128x128x8, 256 threads, 8x8 per-thread micro-tile.
template <int MODE>
__global__ __launch_bounds__(256) void k_sgemm() {
    const int K   = (MODE == 0) ? KP : NPIX;
    const int lda = (MODE == 0) ? KP : NPIX;
    const int ldb = (MODE == 0) ? KP : NJ;
    const int ldc = (MODE == 0) ? NPIX : NJ;
    const size_t z = blockIdx.z;
    const float* A = (MODE == 0) ? (g_P + z * ((size_t)NPIX * KP))
                                 : (g_att + z * ((size_t)NPIX * NPIX));
    const float* B = (MODE == 0) ? (g_P + z * ((size_t)NPIX * KP))
                                 : (g_W + z * ((size_t)NPIX * NJ));
    float* C       = (MODE == 0) ? (g_S + z * ((size_t)NPIX * NPIX))
                                 : (g_T + z * ((size_t)NPIX * NJ));

    const int n0 = blockIdx.x * 128;
    const int m0 = blockIdx.y * 128;

    __shared__ float As[8][128];
    __shared__ float Bs[8][128];

    const int t = threadIdx.x;
    const int tx = t & 15;            // 0..15 -> N sub
    const int ty = t >> 4;            // 0..15 -> M sub
    const int bk_row = t >> 5;        // 0..7
    const int bk_col = (t & 31) * 4;  // 0..124
    const int a_row = t >> 1;         // 0..127
    const int a_col4 = (t & 1) * 4;   // 0 or 4

    float acc[8][8];
    #pragma unroll
    for (int i = 0; i < 8; i++)
        #pragma unroll
        for (int j = 0; j < 8; j++) acc[i][j] = 0.f;

    for (int k0 = 0; k0 < K; k0 += 8) {
        // A is row-major [M][K] in both modes
        {
            float4 va = *(const float4*)&A[(size_t)(m0 + a_row) * lda + k0 + a_col4];
            As[a_col4 + 0][a_row] = va.x;
            As[a_col4 + 1][a_row] = va.y;
            As[a_col4 + 2][a_row] = va.z;
            As[a_col4 + 3][a_row] = va.w;
        }
        if (MODE == 0) {
            // B accessed as [N][K] (transposed)
            float4 vb = *(const float4*)&B[(size_t)(n0 + a_row) * ldb + k0 + a_col4];
            Bs[a_col4 + 0][a_row] = vb.x;
            Bs[a_col4 + 1][a_row] = vb.y;
            Bs[a_col4 + 2][a_row] = vb.z;
            Bs[a_col4 + 3][a_row] = vb.w;
        } else {
            // B row-major [K][N]
            float4 vb = *(const float4*)&B[(size_t)(k0 + bk_row) * ldb + n0 + bk_col];
            *(float4*)&Bs[bk_row][bk_col] = vb;
        }
        __syncthreads();

        #pragma unroll
        for (int kk = 0; kk < 8; kk++) {
            float a[8], b[8];
            *(float4*)(a + 0) = *(float4*)&As[kk][ty * 8 + 0];
            *(float4*)(a + 4) = *(float4*)&As[kk][ty * 8 + 4];
            *(float4*)(b + 0) = *(float4*)&Bs[kk][tx * 8 + 0];
            *(float4*)(b + 4) = *(float4*)&Bs[kk][tx * 8 + 4];
            #pragma unroll
            for (int i = 0; i < 8; i++)
                #pragma unroll
                for (int j = 0; j < 8; j++) acc[i][j] += a[i] * b[j];
        }
        __syncthreads();
    }

    #pragma unroll
    for (int i = 0; i < 8; i++) {
        float* crow = &C[(size_t)(m0 + ty * 8 + i) * ldc + n0 + tx * 8];
        *(float4*)(crow + 0) = *(float4*)&acc[i][0];
        *(float4*)(crow + 4) = *(float4*)&acc[i][4];
    }
}

// ---------------- K3: im2col of x1 (kernel 4, stride 2, pad 1) ----------------
__global__ __launch_bounds__(256) void k_im2col(const float* __restrict__ x1) {
    int q = blockIdx.x;
    int n = blockIdx.y;
    int qy = q / W2, qx = q % W2;
    size_t base = ((size_t)n * NPIX + q) * NJ;
    for (int j = threadIdx.x; j < NJ; j += 256) {
        int c = j & 127;
        int ab = j >> 7;
        int a = ab >> 2, b = ab & 3;
        int ry = 2 * qy + a - 1;
        int rx = 2 * qx + b - 1;
        float v = 0.f;
        if ((unsigned)ry < H1 && (unsigned)rx < W1)
            v = x1[((size_t)(n * CCH + c) * H1 + ry) * W1 + rx];
        g_W[base + j] = v;
    }
}

// ---------------- K4: fused softmax + boost + remask (denom & mm inlined) ----------------
__global__ __launch_bounds__(256) void k_attn(const float* __restrict__ mA,
                                              const float* __restrict__ mB) {
    const float* maskb   = (g_sel == 0) ? mA : mB;   // binary hole mask
    const float* maskall = (g_sel == 0) ? mB : mA;   // non-binary
    const int p = blockIdx.x;       // spatial position (softmax over q for fixed p)
    const int n = blockIdx.y;
    const int py = p / W2, px = p % W2;
    const int t = threadIdx.x;

    __shared__ float red[8];
    __shared__ float bcast;

    const float ma = maskall[n * NPIX + p];
    const float* Sb = g_S + (size_t)n * NPIX * NPIX;
    const float* Srow = Sb + (size_t)p * NPIX;

    float z[9];
    float mmv[9];
    #pragma unroll
    for (int i = 0; i < 9; i++) {
        int q = i * 256 + t;
        int qy = q / W2, qx = q % W2;

        // mm_q: 1 iff the 3x3 (zero-padded) patch of the binary mask is all zero
        float ms = 0.f;
        #pragma unroll
        for (int dy = -1; dy <= 1; dy++) {
            int ry = qy + dy;
            if ((unsigned)ry >= H2) continue;
            #pragma unroll
            for (int dx = -1; dx <= 1; dx++) {
                int rx = qx + dx;
                if ((unsigned)rx < W2)
                    ms += maskb[n * NPIX + ry * W2 + rx];
            }
        }
        float mq = (ms == 0.0f) ? 1.0f : 0.0f;

        // denom_q from Gram diagonal
        float denom = fmaxf(sqrtf(Sb[(size_t)q * NPIX + q]), 1e-4f);

        mmv[i] = mq;
        z[i] = Srow[q] / denom * mq * ma * 10.0f;
    }

    // block max
    float m = z[0];
    #pragma unroll
    for (int i = 1; i < 9; i++) m = fmaxf(m, z[i]);
    #pragma unroll
    for (int o = 16; o > 0; o >>= 1) m = fmaxf(m, __shfl_xor_sync(0xffffffffu, m, o));
    if ((t & 31) == 0) red[t >> 5] = m;
    __syncthreads();
    if (t == 0) {
        float mm = red[0];
        #pragma unroll
        for (int w = 1; w < 8; w++) mm = fmaxf(mm, red[w]);
        bcast = mm;
    }
    __syncthreads();
    const float zmax = bcast;
    __syncthreads();

    float e[9];
    float es = 0.f;
    #pragma unroll
    for (int i = 0; i < 9; i++) {
        e[i] = __expf(z[i] - zmax);
        es += e[i];
    }
    #pragma unroll
    for (int o = 16; o > 0; o >>= 1) es += __shfl_xor_sync(0xffffffffu, es, o);
    if ((t & 31) == 0) red[t >> 5] = es;
    __syncthreads();
    if (t == 0) {
        float ss = 0.f;
        #pragma unroll
        for (int w = 0; w < 8; w++) ss += red[w];
        bcast = ss;
    }
    __syncthreads();
    const float inv = 1.0f / bcast;

    float* arow = g_att + (size_t)n * NPIX * NPIX + (size_t)p * NPIX;
    #pragma unroll
    for (int i = 0; i < 9; i++) {
        int q = i * 256 + t;
        float v = e[i] * inv;
        bool nb = (q == p - 1 && px > 0) || (q == p + 1 && px < W2 - 1) ||
                  (q == p - W2 && py > 0) || (q == p + W2 && py < H2 - 1);
        if (nb) v *= 1.5f;
        v = v * mmv[i] * ma;
        arow[q] = (v >= 1e-8f) ? v : 1e-8f;   // NaN-explicit clamp
    }
}

// ---------------- K6: col2im (transposed-conv gather) ----------------
__global__ __launch_bounds__(128) void k_col2im() {
    int o = blockIdx.x;             // 0..9215
    int n = blockIdx.y;
    int c = threadIdx.x;            // 0..127
    int oy = o / W1, ox = o % W1;
    int a0 = (oy + 1) & 1, b0 = (ox + 1) & 1;
    const float* Tb = g_T + (size_t)n * NPIX * NJ;
    float s = 0.f;
    #pragma unroll
    for (int da = 0; da < 2; da++) {
        int a = a0 + 2 * da;
        int iy2 = oy + 1 - a;
        if (iy2 < 0) continue;
        int iy = iy2 >> 1;
        if (iy >= H2) continue;
        #pragma unroll
        for (int db = 0; db < 2; db++) {
            int b = b0 + 2 * db;
            int ix2 = ox + 1 - b;
            if (ix2 < 0) continue;
            int ix = ix2 >> 1;
            if (ix >= W2) continue;
            s += Tb[(size_t)(iy * W2 + ix) * NJ + (a * 4 + b) * 128 + c];
        }
    }
    g_y[((size_t)(n * CCH + c)) * OPIX + o] = 0.25f * s;
}

// ---------------- K7: fused group dilated 3x3 convs + bias + relu ----------------
__global__ __launch_bounds__(128) void k_fuse(const float* __restrict__ fw,
                                              const float* __restrict__ fb,
                                              float* __restrict__ out) {
    const int chunk = blockIdx.x;   // 0..17 (512 pixels each)
    const int g = blockIdx.y;       // 0..3
    const int n = blockIdx.z;
    const int t = threadIdx.x;      // 0..127
    const int d = 1 << g;

    __shared__ float sfw[32 * 9 * 16];  // [c_local][tap][oc]

    int P[4], OY[4], OX[4];
    #pragma unroll
    for (int i = 0; i < 4; i++) {
        P[i] = chunk * 512 + i * 128 + t;
        OY[i] = P[i] / W1;
        OX[i] = P[i] % W1;
    }

    float acc[4][16];
    #pragma unroll
    for (int i = 0; i < 4; i++)
        #pragma unroll
        for (int oc = 0; oc < 16; oc++) acc[i][oc] = 0.f;

    for (int cc0 = 0; cc0 < CCH; cc0 += 32) {
        __syncthreads();
        for (int s = t; s < 32 * 9 * 16; s += 128) {
            int oc = s & 15;
            int tap = (s >> 4) % 9;
            int cl = s / 144;
            sfw[s] = fw[((size_t)(g * 16 + oc) * CCH + cc0 + cl) * 9 + tap];
        }
        __syncthreads();

        for (int cl = 0; cl < 32; cl++) {
            const float* yb = &g_y[((size_t)(n * CCH + cc0 + cl)) * OPIX];
            #pragma unroll
            for (int tap = 0; tap < 9; tap++) {
                int ky = tap / 3 - 1, kx = tap % 3 - 1;
                float yv[4];
                #pragma unroll
                for (int i = 0; i < 4; i++) {
                    int iy = OY[i] + d * ky, ix = OX[i] + d * kx;
                    yv[i] = ((unsigned)iy < H1 && (unsigned)ix < W1) ? yb[iy * W1 + ix] : 0.f;
                }
                const float* wr = &sfw[cl * 144 + tap * 16];
                #pragma unroll
                for (int oc = 0; oc < 16; oc++) {
                    float w = wr[oc];
                    #pragma unroll
                    for (int i = 0; i < 4; i++) acc[i][oc] += yv[i] * w;
                }
            }
        }
    }

    #pragma unroll
    for (int oc = 0; oc < 16; oc++) {
        float b = fb[g * 16 + oc];
        #pragma unroll
        for (int i = 0; i < 4; i++) {
            out[((size_t)(n * 64 + g * 16 + oc)) * OPIX + P[i]] = fmaxf(acc[i][oc] + b, 0.f);
        }
    }
}

// ---------------- launch ----------------
extern "C" void kernel_launch(void* const* d_in, const int* in_sizes, int n_in,
                              void* d_out, int out_size) {
    // Identify inputs by element count; the two 4608-element tensors (mask vs
    // mask_all) are disambiguated ON DEVICE by content (mask is binary).
    const float* x1 = 0;
    const float* x2 = 0;
    const float* mA = 0;   // first 4608 tensor
    const float* mB = 0;   // second 4608 tensor
    const float* fuse_w = 0;
    const float* fuse_b = 0;
    for (int i = 0; i < n_in; i++) {
        int sz = in_sizes[i];
        const float* p = (const float*)d_in[i];
        if (sz == 2359296) x1 = p;
        else if (sz == 589824) x2 = p;
        else if (sz == 73728) fuse_w = p;
        else if (sz == 64) fuse_b = p;
        else if (sz == 4608) {
            if (!mA) mA = p;
            else mB = p;
        }
    }
    if (!x1 || !x2 || !mA || !mB || !fuse_w || !fuse_b) {
        x1 = (const float*)d_in[0];
        x2 = (const float*)d_in[1];
        mA = (const float*)d_in[2];
        mB = (const float*)d_in[3];
        fuse_w = (const float*)d_in[4];
        fuse_b = (const float*)d_in[5];
    }
    float* out = (float*)d_out;                     // (2,64,96,96)

    // 0. decide which 4608-tensor is the binary mask
    k_detect<<<1, 256>>>(mA);

    // 1. P = im2col3(x2)  [2304 x 1152] per batch
    k_im2col3<<<dim3(NPIX, NB), 256>>>(x2);

    // 2. S = P P^T : M=N=2304, K=1152   (operands resolved in device code)
    k_sgemm<0><<<dim3(18, 18, NB), 256>>>();

    // 3. im2col of x1 (independent; before paste GEMM)
    k_im2col<<<dim3(NPIX, NB), 256>>>(x1);

    // 4. softmax + boost + remask (denom & mm computed inline from S diag + mask)
    k_attn<<<dim3(NPIX, NB), 256>>>(mA, mB);

    // 5. paste GEMM: T = att * W; M=2304, N=2048, K=2304
    k_sgemm<1><<<dim3(16, 18, NB), 256>>>();

    // 6. col2im + /4
    k_col2im<<<dim3(OPIX, NB), 128>>>();

    // 7. fuse convs
    k_fuse<<<dim3(18, 4, NB), 128>>>(fuse_w, fuse_b, out);
}

// round 13
// speedup vs baseline: 1.4254x; 1.4254x over previous
#include <cuda_runtime.h>
#include <cuda_bf16.h>
#include <math.h>

// Problem constants
#define H2 48
#define W2 48
#define NPIX 2304           // 48*48
#define CCH 128             // channels
#define NB 2                // batch
#define H1 96
#define W1 96
#define NJ 2048             // 16 * 128  ((a,b) x c)
#define OPIX 9216           // 96*96

typedef unsigned long long u64;

// ---------------- scratch (device globals; referenced ONLY from device code) ----------------
__device__ __align__(16) float g_C[(size_t)NB * NPIX * NPIX];     // pixel gram C = X^T X [n][p][q]
__device__ __align__(16) float g_att[(size_t)NB * NPIX * NPIX];   // attention   [n][pix][q]
__device__ __align__(16) float g_W[(size_t)NB * NPIX * NJ];       // im2col(x1)  [n][q][(a*4+b)*128+c]
__device__ __align__(16) float g_T[(size_t)NB * NPIX * NJ];       // gemm out    [n][pix][(a*4+b)*128+c]
__device__ __align__(16) float g_y[(size_t)NB * CCH * OPIX];      // paste result [n][c][96*96]
__device__ float g_s2[NB * NPIX];                                 // per-pixel channel sumsq
__device__ int g_sel;   // 0: first 4608-tensor is binary mask; 1: it's mask_all

// ---------------- packed f32x2 helpers ----------------
__device__ __forceinline__ u64 pack2(float lo, float hi) {
    u64 r; asm("mov.b64 %0, {%1, %2};" : "=l"(r) : "f"(lo), "f"(hi)); return r;
}
__device__ __forceinline__ void fma2(u64& d, u64 a, u64 b) {
    asm("fma.rn.f32x2 %0, %1, %2, %0;" : "+l"(d) : "l"(a), "l"(b));
}
__device__ __forceinline__ float2 unpack2(u64 v) {
    float2 f; asm("mov.b64 {%0, %1}, %2;" : "=f"(f.x), "=f"(f.y) : "l"(v)); return f;
}

// ---------------- K0: detect which 4608-tensor is the binary mask ----------------
__global__ __launch_bounds__(256) void k_detect(const float* __restrict__ mA) {
    __shared__ int nonbin;
    if (threadIdx.x == 0) nonbin = 0;
    __syncthreads();
    int local = 0;
    for (int i = threadIdx.x; i < NB * NPIX; i += 256) {
        float v = mA[i];
        if (v != 0.0f && v != 1.0f) local = 1;
    }
    if (local) atomicOr(&nonbin, 1);
    __syncthreads();
    if (threadIdx.x == 0) g_sel = nonbin;   // nonbinary -> mA is mask_all
}

// ---------------- K1: per-pixel channel sum of squares ----------------
__global__ __launch_bounds__(256) void k_s2(const float* __restrict__ x2) {
    int p = blockIdx.x * 256 + threadIdx.x;       // < 2304
    int n = blockIdx.y;
    float s = 0.f;
    #pragma unroll 4
    for (int c = 0; c < CCH; c++) {
        float v = x2[((size_t)(n * CCH + c)) * NPIX + p];
        s += v * v;
    }
    g_s2[n * NPIX + p] = s;
}

// ---------------- tiled SGEMM (FFMA2 microkernel) ----------------
// MODE 0 (gram):  C=g_C[2304x2304] = X^T X, X = x2 stored [K=128][M=2304] per batch
// MODE 1 (paste): C=g_T[2304xNJ]   = g_att[2304x2304(row-major MxK)] * g_W[2304xNJ (KxN)]
// Tiles 128x128x8, 256 threads, 8(M)x8(N) per-thread micro-tile, M paired for f32x2.
template <int MODE>
__global__ __launch_bounds__(256) void k_sgemm(const float* __restrict__ Xin) {
    const int K   = (MODE == 0) ? CCH : NPIX;
    const int lda = (MODE == 0) ? NPIX : NPIX;
    const int ldb = (MODE == 0) ? NPIX : NJ;
    const int ldc = (MODE == 0) ? NPIX : NJ;
    const size_t z = blockIdx.z;
    const float* A = (MODE == 0) ? (Xin + z * ((size_t)CCH * NPIX))
                                 : (g_att + z * ((size_t)NPIX * NPIX));
    const float* B = (MODE == 0) ? (Xin + z * ((size_t)CCH * NPIX))
                                 : (g_W + z * ((size_t)NPIX * NJ));
    float* C       = (MODE == 0) ? (g_C + z * ((size_t)NPIX * NPIX))
                                 : (g_T + z * ((size_t)NPIX * NJ));

    const int n0 = blockIdx.x * 128;
    const int m0 = blockIdx.y * 128;

    __shared__ float As[8][128];
    __shared__ float Bs[8][128];

    const int t = threadIdx.x;
    const int tx = t & 15;            // 0..15 -> N sub
    const int ty = t >> 4;            // 0..15 -> M sub
    const int bk_row = t >> 5;        // 0..7
    const int bk_col = (t & 31) * 4;  // 0..124
    const int a_row = t >> 1;         // 0..127
    const int a_col4 = (t & 1) * 4;   // 0 or 4

    u64 acc2[4][8];
    #pragma unroll
    for (int i = 0; i < 4; i++)
        #pragma unroll
        for (int j = 0; j < 8; j++) acc2[i][j] = 0ull;

    for (int k0 = 0; k0 < K; k0 += 8) {
        if (MODE == 0) {
            // X stored [K][M]: direct tile loads for both operands
            float4 va = *(const float4*)&A[(size_t)(k0 + bk_row) * lda + m0 + bk_col];
            *(float4*)&As[bk_row][bk_col] = va;
            float4 vb = *(const float4*)&B[(size_t)(k0 + bk_row) * ldb + n0 + bk_col];
            *(float4*)&Bs[bk_row][bk_col] = vb;
        } else {
            // A row-major [M][K]: transpose into As
            float4 va = *(const float4*)&A[(size_t)(m0 + a_row) * lda + k0 + a_col4];
            As[a_col4 + 0][a_row] = va.x;
            As[a_col4 + 1][a_row] = va.y;
            As[a_col4 + 2][a_row] = va.z;
            As[a_col4 + 3][a_row] = va.w;
            // B row-major [K][N]
            float4 vb = *(const float4*)&B[(size_t)(k0 + bk_row) * ldb + n0 + bk_col];
            *(float4*)&Bs[bk_row][bk_col] = vb;
        }
        __syncthreads();

        #pragma unroll
        for (int kk = 0; kk < 8; kk++) {
            float a[8], b[8];
            *(float4*)(a + 0) = *(float4*)&As[kk][ty * 8 + 0];
            *(float4*)(a + 4) = *(float4*)&As[kk][ty * 8 + 4];
            *(float4*)(b + 0) = *(float4*)&Bs[kk][tx * 8 + 0];
            *(float4*)(b + 4) = *(float4*)&Bs[kk][tx * 8 + 4];
            u64 ap[4], bp[8];
            #pragma unroll
            for (int i = 0; i < 4; i++) ap[i] = pack2(a[2 * i], a[2 * i + 1]);
            #pragma unroll
            for (int j = 0; j < 8; j++) bp[j] = pack2(b[j], b[j]);
            #pragma unroll
            for (int i = 0; i < 4; i++)
                #pragma unroll
                for (int j = 0; j < 8; j++) fma2(acc2[i][j], ap[i], bp[j]);
        }
        __syncthreads();
    }

    #pragma unroll
    for (int i = 0; i < 4; i++) {
        float r0[8], r1[8];
        #pragma unroll
        for (int j = 0; j < 8; j++) {
            float2 v = unpack2(acc2[i][j]);
            r0[j] = v.x;
            r1[j] = v.y;
        }
        float* c0 = &C[(size_t)(m0 + ty * 8 + 2 * i + 0) * ldc + n0 + tx * 8];
        float* c1 = &C[(size_t)(m0 + ty * 8 + 2 * i + 1) * ldc + n0 + tx * 8];
        *(float4*)(c0 + 0) = *(float4*)&r0[0];
        *(float4*)(c0 + 4) = *(float4*)&r0[4];
        *(float4*)(c1 + 0) = *(float4*)&r1[0];
        *(float4*)(c1 + 4) = *(float4*)&r1[4];
    }
}

// ---------------- K3: im2col of x1 (kernel 4, stride 2, pad 1) ----------------
__global__ __launch_bounds__(256) void k_im2col(const float* __restrict__ x1) {
    int q = blockIdx.x;
    int n = blockIdx.y;
    int qy = q / W2, qx = q % W2;
    size_t base = ((size_t)n * NPIX + q) * NJ;
    for (int j = threadIdx.x; j < NJ; j += 256) {
        int c = j & 127;
        int ab = j >> 7;
        int a = ab >> 2, b = ab & 3;
        int ry = 2 * qy + a - 1;
        int rx = 2 * qx + b - 1;
        float v = 0.f;
        if ((unsigned)ry < H1 && (unsigned)rx < W1)
            v = x1[((size_t)(n * CCH + c) * H1 + ry) * W1 + rx];
        g_W[base + j] = v;
    }
}

// ---------------- K4: score assembly from gram + softmax + boost + remask ----------------
__global__ __launch_bounds__(256) void k_attn(const float* __restrict__ mA,
                                              const float* __restrict__ mB) {
    const float* maskb   = (g_sel == 0) ? mA : mB;   // binary hole mask
    const float* maskall = (g_sel == 0) ? mB : mA;   // non-binary
    const int p = blockIdx.x;       // spatial position (softmax over q for fixed p)
    const int n = blockIdx.y;
    const int py = p / W2, px = p % W2;
    const int t = threadIdx.x;

    __shared__ float red[8];
    __shared__ float bcast;

    const float ma = maskall[n * NPIX + p];
    const float* Cb = g_C + (size_t)n * NPIX * NPIX;

    float z[9];
    float mmv[9];
    #pragma unroll
    for (int i = 0; i < 9; i++) {
        int q = i * 256 + t;
        int qy = q / W2, qx = q % W2;

        // mm_q (mask-patch-all-zero flag) and denom_q (patch norm) share bounds
        float ms = 0.f, d2 = 0.f;
        #pragma unroll
        for (int dy = -1; dy <= 1; dy++) {
            int ry = qy + dy;
            if ((unsigned)ry >= H2) continue;
            #pragma unroll
            for (int dx = -1; dx <= 1; dx++) {
                int rx = qx + dx;
                if ((unsigned)rx < W2) {
                    int idx = n * NPIX + ry * W2 + rx;
                    ms += maskb[idx];
                    d2 += g_s2[idx];
                }
            }
        }
        float mq = (ms == 0.0f) ? 1.0f : 0.0f;
        float denom = fmaxf(sqrtf(d2), 1e-4f);

        // score S[p][q] = sum over valid offsets o of C[p+o, q+o]
        float s = 0.f;
        #pragma unroll
        for (int dy = -1; dy <= 1; dy++) {
            int ry = py + dy, sy = qy + dy;
            if ((unsigned)ry >= H2 || (unsigned)sy >= H2) continue;
            #pragma unroll
            for (int dx = -1; dx <= 1; dx++) {
                int rx = px + dx, sx = qx + dx;
                if ((unsigned)rx < W2 && (unsigned)sx < W2)
                    s += Cb[(size_t)(ry * W2 + rx) * NPIX + sy * W2 + sx];
            }
        }

        mmv[i] = mq;
        z[i] = s / denom * mq * ma * 10.0f;
    }

    // block max
    float m = z[0];
    #pragma unroll
    for (int i = 1; i < 9; i++) m = fmaxf(m, z[i]);
    #pragma unroll
    for (int o = 16; o > 0; o >>= 1) m = fmaxf(m, __shfl_xor_sync(0xffffffffu, m, o));
    if ((t & 31) == 0) red[t >> 5] = m;
    __syncthreads();
    if (t == 0) {
        float mm = red[0];
        #pragma unroll
        for (int w = 1; w < 8; w++) mm = fmaxf(mm, red[w]);
        bcast = mm;
    }
    __syncthreads();
    const float zmax = bcast;
    __syncthreads();

    float e[9];
    float es = 0.f;
    #pragma unroll
    for (int i = 0; i < 9; i++) {
        e[i] = __expf(z[i] - zmax);
        es += e[i];
    }
    #pragma unroll
    for (int o = 16; o > 0; o >>= 1) es += __shfl_xor_sync(0xffffffffu, es, o);
    if ((t & 31) == 0) red[t >> 5] = es;
    __syncthreads();
    if (t == 0) {
        float ss = 0.f;
        #pragma unroll
        for (int w = 0; w < 8; w++) ss += red[w];
        bcast = ss;
    }
    __syncthreads();
    const float inv = 1.0f / bcast;

    float* arow = g_att + (size_t)n * NPIX * NPIX + (size_t)p * NPIX;
    #pragma unroll
    for (int i = 0; i < 9; i++) {
        int q = i * 256 + t;
        float v = e[i] * inv;
        bool nb = (q == p - 1 && px > 0) || (q == p + 1 && px < W2 - 1) ||
                  (q == p - W2 && py > 0) || (q == p + W2 && py < H2 - 1);
        if (nb) v *= 1.5f;
        v = v * mmv[i] * ma;
        arow[q] = (v >= 1e-8f) ? v : 1e-8f;   // NaN-explicit clamp
    }
}

// ---------------- K6: col2im (transposed-conv gather) ----------------
__global__ __launch_bounds__(128) void k_col2im() {
    int o = blockIdx.x;             // 0..9215
    int n = blockIdx.y;
    int c = threadIdx.x;            // 0..127
    int oy = o / W1, ox = o % W1;
    int a0 = (oy + 1) & 1, b0 = (ox + 1) & 1;
    const float* Tb = g_T + (size_t)n * NPIX * NJ;
    float s = 0.f;
    #pragma unroll
    for (int da = 0; da < 2; da++) {
        int a = a0 + 2 * da;
        int iy2 = oy + 1 - a;
        if (iy2 < 0) continue;
        int iy = iy2 >> 1;
        if (iy >= H2) continue;
        #pragma unroll
        for (int db = 0; db < 2; db++) {
            int b = b0 + 2 * db;
            int ix2 = ox + 1 - b;
            if (ix2 < 0) continue;
            int ix = ix2 >> 1;
            if (ix >= W2) continue;
            s += Tb[(size_t)(iy * W2 + ix) * NJ + (a * 4 + b) * 128 + c];
        }
    }
    g_y[((size_t)(n * CCH + c)) * OPIX + o] = 0.25f * s;
}

// ---------------- K7: fused group dilated 3x3 convs + bias + relu ----------------
__global__ __launch_bounds__(128) void k_fuse(const float* __restrict__ fw,
                                              const float* __restrict__ fb,
                                              float* __restrict__ out) {
    const int chunk = blockIdx.x;   // 0..17 (512 pixels each)
    const int g = blockIdx.y;       // 0..3
    const int n = blockIdx.z;
    const int t = threadIdx.x;      // 0..127
    const int d = 1 << g;

    __shared__ float sfw[32 * 9 * 16];  // [c_local][tap][oc]

    int P[4], OY[4], OX[4];
    #pragma unroll
    for (int i = 0; i < 4; i++) {
        P[i] = chunk * 512 + i * 128 + t;
        OY[i] = P[i] / W1;
        OX[i] = P[i] % W1;
    }

    float acc[4][16];
    #pragma unroll
    for (int i = 0; i < 4; i++)
        #pragma unroll
        for (int oc = 0; oc < 16; oc++) acc[i][oc] = 0.f;

    for (int cc0 = 0; cc0 < CCH; cc0 += 32) {
        __syncthreads();
        for (int s = t; s < 32 * 9 * 16; s += 128) {
            int oc = s & 15;
            int tap = (s >> 4) % 9;
            int cl = s / 144;
            sfw[s] = fw[((size_t)(g * 16 + oc) * CCH + cc0 + cl) * 9 + tap];
        }
        __syncthreads();

        for (int cl = 0; cl < 32; cl++) {
            const float* yb = &g_y[((size_t)(n * CCH + cc0 + cl)) * OPIX];
            #pragma unroll
            for (int tap = 0; tap < 9; tap++) {
                int ky = tap / 3 - 1, kx = tap % 3 - 1;
                float yv[4];
                #pragma unroll
                for (int i = 0; i < 4; i++) {
                    int iy = OY[i] + d * ky, ix = OX[i] + d * kx;
                    yv[i] = ((unsigned)iy < H1 && (unsigned)ix < W1) ? yb[iy * W1 + ix] : 0.f;
                }
                const float* wr = &sfw[cl * 144 + tap * 16];
                #pragma unroll
                for (int oc = 0; oc < 16; oc++) {
                    float w = wr[oc];
                    #pragma unroll
                    for (int i = 0; i < 4; i++) acc[i][oc] += yv[i] * w;
                }
            }
        }
    }

    #pragma unroll
    for (int oc = 0; oc < 16; oc++) {
        float b = fb[g * 16 + oc];
        #pragma unroll
        for (int i = 0; i < 4; i++) {
            out[((size_t)(n * 64 + g * 16 + oc)) * OPIX + P[i]] = fmaxf(acc[i][oc] + b, 0.f);
        }
    }
}

// ---------------- launch ----------------
extern "C" void kernel_launch(void* const* d_in, const int* in_sizes, int n_in,
                              void* d_out, int out_size) {
    const float* x1 = 0;
    const float* x2 = 0;
    const float* mA = 0;   // first 4608 tensor
    const float* mB = 0;   // second 4608 tensor
    const float* fuse_w = 0;
    const float* fuse_b = 0;
    for (int i = 0; i < n_in; i++) {
        int sz = in_sizes[i];
        const float* p = (const float*)d_in[i];
        if (sz == 2359296) x1 = p;
        else if (sz == 589824) x2 = p;
        else if (sz == 73728) fuse_w = p;
        else if (sz == 64) fuse_b = p;
        else if (sz == 4608) {
            if (!mA) mA = p;
            else mB = p;
        }
    }
    if (!x1 || !x2 || !mA || !mB || !fuse_w || !fuse_b) {
        x1 = (const float*)d_in[0];
        x2 = (const float*)d_in[1];
        mA = (const float*)d_in[2];
        mB = (const float*)d_in[3];
        fuse_w = (const float*)d_in[4];
        fuse_b = (const float*)d_in[5];
    }
    float* out = (float*)d_out;                     // (2,64,96,96)

    // 0. decide which 4608-tensor is the binary mask
    k_detect<<<1, 256>>>(mA);

    // 1. per-pixel sum of squares (for patch norms)
    k_s2<<<dim3(9, NB), 256>>>(x2);

    // 2. pixel gram C = X^T X : M=N=2304, K=128 (9x fewer FLOPs than patch GEMM)
    k_sgemm<0><<<dim3(18, 18, NB), 256>>>(x2);

    // 3. im2col of x1 (independent; before paste GEMM)
    k_im2col<<<dim3(NPIX, NB), 256>>>(x1);

    // 4. score assembly (diagonal shifts of C) + softmax + boost + remask
    k_attn<<<dim3(NPIX, NB), 256>>>(mA, mB);

    // 5. paste GEMM: T = att * W; M=2304, N=2048, K=2304 (FFMA2)
    k_sgemm<1><<<dim3(16, 18, NB), 256>>>(0);

    // 6. col2im + /4
    k_col2im<<<dim3(OPIX, NB), 128>>>();

    // 7. fuse convs
    k_fuse<<<dim3(18, 4, NB), 128>>>(fuse_w, fuse_b, out);
}